// round 15
// baseline (speedup 1.0000x reference)
#include <cuda_runtime.h>
#include <math.h>
#include <limits.h>

#define S_STAGES 3
#define BATCH    32
#define NPRIOR   2000
#define LANES    4
#define DFEAT    78          // 2 + 4 + 72
#define NOFF     72
#define SB       96
#define IMG_W_F  800.0f
#define IMG_W1_F 799.0f
#define TILE     128
#define NTILE    16          // 15 full tiles + one of 80
#define ROWB     312         // bytes per row
#define NCAND    (NTILE * 4) // 64 candidates per column
#define NMATCH   (2 * SB * LANES)   // 768
#define NTASK    (2 * SB)           // 192
#define FIXSCALE 1099511627776.0f   // 2^40

// Scratch (device globals — no allocation allowed)
// g_cls_acc is zero at load; final_kernel re-zeroes after consuming (replay-safe).
__device__ unsigned long long g_cls_acc[2 * NPRIOR];
__device__ float g_cv[NTASK * LANES * NCAND];
__device__ int   g_ci[NTASK * LANES * NCAND];
__device__ int   g_rows[NMATCH];
__device__ float g_reg [NMATCH];
__device__ float g_iou [NMATCH];
__device__ float g_corr[NMATCH];

// ---------------------------------------------------------------------------
// Kernel 1: TMA bulk-copy staged cost. 512 threads, 4 threads per row
// (k-loop split in quarters), partials exchanged via SMEM.
// grid (96, NTILE, 2). 4 blocks/SM = 64 warps (thread cap).
// ---------------------------------------------------------------------------
__global__ __launch_bounds__(512, 4) void cost_kernel(
    const float* __restrict__ predA,
    const float* __restrict__ predB,
    const float* __restrict__ gt)
{
    const int sb     = blockIdx.x;
    const int tile   = blockIdx.y;
    const int branch = blockIdx.z;
    const int n0     = tile * TILE;
    const int T      = (n0 + TILE <= NPRIOR) ? TILE : (NPRIOR - n0);
    const float* __restrict__ pred = branch ? predB : predA;
    const int b = sb % BATCH;
    const char* gbase = (const char*)(pred + ((size_t)sb * NPRIOR + n0) * DFEAT);
    const size_t bs = (size_t)branch * SB + sb;

    __shared__ __align__(16) char  sh_buf[TILE * ROWB];   // 39936 B, linear
    __shared__ __align__(16) float sh_gt8[39][8];
    __shared__ float sh_geo[LANES][4];
    __shared__ float sh_acc[LANES][TILE];                 // final costs
    __shared__ float sh_red[3][LANES][TILE];              // q1..q3 partials
    __shared__ float sh_sc[TILE];                         // per-row score
    __shared__ __align__(8) unsigned long long sh_mbar;

    const int tid  = threadIdx.x;
    const int warp = tid >> 5, lane = tid & 31;
    const unsigned FULL = 0xffffffffu;
    const unsigned sp   = (unsigned)__cvta_generic_to_shared(sh_buf);
    const unsigned mb   = (unsigned)__cvta_generic_to_shared(&sh_mbar);
    const unsigned tile_bytes = (unsigned)(T * ROWB);

    if (tid == 0)
        asm volatile("mbarrier.init.shared.b64 [%0], 1;" :: "r"(mb) : "memory");
    __syncthreads();

    if (tid == 0) {
        asm volatile("mbarrier.arrive.expect_tx.shared.b64 _, [%0], %1;"
                     :: "r"(mb), "r"(tile_bytes) : "memory");
        asm volatile("cp.async.bulk.shared::cta.global.mbarrier::complete_tx::bytes "
                     "[%0], [%1], %2, [%3];"
                     :: "r"(sp), "l"(gbase), "r"(tile_bytes), "r"(mb) : "memory");
    }

    // gt tables (overlap with bulk DMA)
    for (int i = tid; i < 39 * 8; i += 512) {
        int k = i >> 3, j = i & 7;
        int l = j >> 1, comp = j & 1;
        int d = 2 * k + comp;
        float v = 0.0f;
        if (d >= 6 && d < DFEAT)
            v = gt[((size_t)b * LANES + l) * DFEAT + d] * (1.0f / IMG_W1_F);
        sh_gt8[k][j] = v;
    }
    if (tid < 16)
        sh_geo[tid >> 2][tid & 3] =
            gt[((size_t)b * LANES + (tid >> 2)) * DFEAT + 2 + (tid & 3)];

    // wait for bulk copy (parity 0)
    {
        unsigned done;
        asm volatile(
            "{\n\t.reg .pred p;\n\t"
            "mbarrier.try_wait.parity.shared.b64 p, [%1], 0;\n\t"
            "selp.b32 %0, 1, 0, p;\n\t}"
            : "=r"(done) : "r"(mb) : "memory");
        while (!done) {
            asm volatile(
                "{\n\t.reg .pred p;\n\t"
                "mbarrier.try_wait.parity.shared.b64 p, [%1], 0, 0x989680;\n\t"
                "selp.b32 %0, 1, 0, p;\n\t}"
                : "=r"(done) : "r"(mb) : "memory");
        }
    }
    __syncthreads();

    // ---- compute: 4 threads per row, quarter q handles k = 3+9q .. 3+9q+8
    const int row = tid & 127;
    const int q   = tid >> 7;
    const char* rb = sh_buf + row * ROWB;

    float o[LANES] = {0.0f, 0.0f, 0.0f, 0.0f};
    float cg[LANES];
    if (row < T) {
        const int k0 = 3 + q * 9;
        #pragma unroll
        for (int kk = 0; kk < 9; kk++) {
            const int k = k0 + kk;
            float2 pv = *(const float2*)(rb + k * 8);
            float4 ga = *(const float4*)&sh_gt8[k][0];
            float4 gb = *(const float4*)&sh_gt8[k][4];
            o[0] += fabsf(pv.x - ga.x) + fabsf(pv.y - ga.y);
            o[1] += fabsf(pv.x - ga.z) + fabsf(pv.y - ga.w);
            o[2] += fabsf(pv.x - gb.x) + fabsf(pv.y - gb.y);
            o[3] += fabsf(pv.x - gb.z) + fabsf(pv.y - gb.w);
        }
        if (q == 0) {
            float2 q1v = *(const float2*)(rb + 8);    // d2,d3
            float2 q2v = *(const float2*)(rb + 16);   // d4,d5
            #pragma unroll
            for (int l = 0; l < LANES; l++)
                cg[l] = fabsf(q1v.x - sh_geo[l][0]) + fabsf(q1v.y - sh_geo[l][1])
                      + fabsf(q2v.x - sh_geo[l][2]) + fabsf(q2v.y - sh_geo[l][3]);
        } else {
            #pragma unroll
            for (int l = 0; l < LANES; l++) sh_red[q - 1][l][row] = o[l];
        }
        if (q == 3) {
            float2 q0v = *(const float2*)(rb);        // logits
            float x0 = q0v.x, x1 = q0v.y;
            float m  = fmaxf(x0, x1);
            float e0 = expf(x0 - m), e1 = expf(x1 - m);
            float denom = e0 + e1;
            float score = e1 / denom;
            sh_sc[row] = score;
            float lse = m + logf(denom);
            float om0 = 1.0f - e0 / denom;
            float cneg = -0.1f * om0 * om0 * (x0 - lse);
            atomicAdd(&g_cls_acc[branch * NPRIOR + n0 + row],
                      (unsigned long long)(long long)__float2ll_rn(cneg * FIXSCALE));
        }
    }
    __syncthreads();

    // ---- q0 finalizes cost per row
    if (q == 0) {
        if (row < T) {
            float score = sh_sc[row];
            #pragma unroll
            for (int l = 0; l < LANES; l++) {
                float tot = o[l] + sh_red[0][l][row] + sh_red[1][l][row]
                                 + sh_red[2][l][row];
                sh_acc[l][row] = cg[l] + tot * (1.0f / 72.0f) - score;
            }
        } else {
            #pragma unroll
            for (int l = 0; l < LANES; l++) sh_acc[l][row] = INFINITY;
        }
    }
    __syncthreads();

    // ---- warps 0..3: top-4 of column w within tile, first-index tie-break
    if (warp < LANES) {
        const int w = warp;
        const size_t base = ((bs * LANES + w) * NTILE + tile) * 4;
        #pragma unroll
        for (int pass = 0; pass < 4; pass++) {
            float v = INFINITY; int li = INT_MAX;
            #pragma unroll
            for (int j0 = 0; j0 < TILE; j0 += 32) {
                int j = j0 + lane;
                float cc = sh_acc[w][j];
                if (cc < v || (cc == v && j < li)) { v = cc; li = j; }
            }
            #pragma unroll
            for (int off = 16; off; off >>= 1) {
                float v2 = __shfl_xor_sync(FULL, v, off);
                int   i2 = __shfl_xor_sync(FULL, li, off);
                if (v2 < v || (v2 == v && i2 < li)) { v = v2; li = i2; }
            }
            if (lane == 0) {
                g_cv[base + pass] = v;
                g_ci[base + pass] = n0 + li;
                sh_acc[w][li] = INFINITY;
            }
            __syncwarp(FULL);
        }
    }
}

// ---------------------------------------------------------------------------
// Kernel 2: per-task greedy merge + reg/iou/corr. grid 192, 128 threads.
// ---------------------------------------------------------------------------
__global__ __launch_bounds__(128) void match_kernel(
    const float* __restrict__ predA,
    const float* __restrict__ predB,
    const float* __restrict__ gt)
{
    const int task   = blockIdx.x;             // 0..191
    const int branch = task / SB;
    const int sb     = task % SB;
    const int b      = sb % BATCH;

    __shared__ int rows_sh[LANES];

    const int tid  = threadIdx.x;
    const int warp = tid >> 5, lane = tid & 31;
    const unsigned FULL = 0xffffffffu;

    if (warp == 0) {
        const size_t base = (size_t)task * LANES * NCAND;
        float cv[LANES][2]; int ci[LANES][2];
        #pragma unroll
        for (int col = 0; col < LANES; col++) {
            cv[col][0] = g_cv[base + col * NCAND + lane];
            cv[col][1] = g_cv[base + col * NCAND + 32 + lane];
            ci[col][0] = g_ci[base + col * NCAND + lane];
            ci[col][1] = g_ci[base + col * NCAND + 32 + lane];
        }
        int u0 = -1, u1 = -1, u2 = -1;
        #pragma unroll
        for (int col = 0; col < LANES; col++) {
            float v = INFINITY; int li = INT_MAX;
            #pragma unroll
            for (int k = 0; k < 2; k++) {
                int   i2 = ci[col][k];
                float v2 = cv[col][k];
                bool excl = (i2 == u0) | (i2 == u1) | (i2 == u2);
                if (!excl && (v2 < v || (v2 == v && i2 < li))) { v = v2; li = i2; }
            }
            #pragma unroll
            for (int off = 16; off; off >>= 1) {
                float v2 = __shfl_xor_sync(FULL, v, off);
                int   i2 = __shfl_xor_sync(FULL, li, off);
                if (v2 < v || (v2 == v && i2 < li)) { v = v2; li = i2; }
            }
            if (lane == 0) { rows_sh[col] = li; g_rows[task * LANES + col] = li; }
            if (col == 0) u0 = li; else if (col == 1) u1 = li; else if (col == 2) u2 = li;
        }
    }
    __syncthreads();

    {
        const int l = warp;
        const int r = rows_sh[l];
        const int mm = task * LANES + l;
        const float* p  = (branch ? predB : predA)
                          + ((size_t)sb * NPRIOR + r) * DFEAT;
        const float* tg = gt + ((size_t)b * LANES + l) * DFEAT;

        float ovrS = 0.0f, uniS = 0.0f;
        #pragma unroll
        for (int kb = 0; kb < 3; kb++) {
            int k = kb * 32 + lane;
            if (k < NOFF) {
                float rp = p[6 + k] * IMG_W1_F;
                float rt = tg[6 + k];
                bool invalid = (rt < 0.0f) || (rt >= IMG_W_F);
                float mn = fminf(rp, rt), mx = fmaxf(rp, rt);
                if (!invalid) {
                    ovrS += (mn - mx + 30.0f);
                    uniS += (mx - mn + 30.0f);
                }
            }
        }
        #pragma unroll
        for (int off = 16; off; off >>= 1) {
            ovrS += __shfl_xor_sync(FULL, ovrS, off);
            uniS += __shfl_xor_sync(FULL, uniS, off);
        }
        if (lane == 0) {
            float iou = ovrS / (uniS + 1e-9f);
            g_iou[mm] = (1.0f - iou) * 0.25f;
            const float sc[4] = {71.0f, IMG_W1_F, 180.0f, 71.0f};
            float ssum = 0.0f;
            #pragma unroll
            for (int j = 0; j < 4; j++) {
                float d  = (p[2 + j] - tg[2 + j]) * sc[j];
                float ad = fabsf(d);
                ssum += (ad < 1.0f) ? 0.5f * d * d : ad - 0.5f;
            }
            g_reg[mm] = ssum * 0.0625f;   // mean over 4, /L

            float x0 = p[0], x1 = p[1];
            float m2  = fmaxf(x0, x1);
            float e0 = expf(x0 - m2), e1 = expf(x1 - m2);
            float denom = e0 + e1;
            float lse = m2 + logf(denom);
            float om0 = 1.0f - e0 / denom, om1 = 1.0f - e1 / denom;
            float cneg = -0.1f * om0 * om0 * (x0 - lse);
            float cpos = -0.9f * om1 * om1 * (x1 - lse);
            g_corr[mm] = (cpos - cneg) * (2.0f / 96.0f);
        }
    }
}

// ---------------------------------------------------------------------------
// Kernel 3: inst build + corrections + dual-rank radix median + weighted sum.
// Single block, 1024 threads. reg/iou staged through SMEM.
// ---------------------------------------------------------------------------
__global__ __launch_bounds__(1024) void final_kernel(
    const float* __restrict__ diff,
    float* __restrict__ out)
{
    __shared__ float instA[NPRIOR];
    __shared__ float instB[NPRIOR];
    __shared__ unsigned ukey[NPRIOR];
    __shared__ float reg_sh[NMATCH];
    __shared__ float iou_sh[NMATCH];
    __shared__ int   hist[2][256];
    __shared__ float red[1024];
    __shared__ int   s_bin[2], s_k[2];

    const int tid = threadIdx.x;
    const int warp = tid >> 5, lane = tid & 31;
    const unsigned FULL = 0xffffffffu;

    // cooperative parallel loads: cls accumulators + reg/iou into SMEM
    const float CLS_K = (float)(2.0 / 96.0 / 1099511627776.0);
    for (int n = tid; n < NPRIOR; n += 1024) {
        long long a0 = (long long)g_cls_acc[n];
        long long b0 = (long long)g_cls_acc[NPRIOR + n];
        instA[n] = (float)a0 * CLS_K;
        instB[n] = (float)b0 * CLS_K;
        g_cls_acc[n] = 0ull;
        g_cls_acc[NPRIOR + n] = 0ull;
    }
    if (tid < NMATCH) {
        reg_sh[tid] = g_reg[tid];
        iou_sh[tid] = g_iou[tid];
    }
    __syncthreads();

    // matched-row focal corrections (parallel, 768 threads)
    if (tid < NMATCH) {
        const int branch = tid / (SB * LANES);
        const int r = g_rows[tid];
        atomicAdd(branch == 0 ? &instA[r] : &instB[r], g_corr[tid]);
    }
    // reg/iou sums from SMEM: 64 threads, 8 lanes per (branch,l) group
    if (tid >= 960 && tid < 1024) {
        const int t = tid - 960;
        const int g = t >> 3;              // 0..7 = branch*4 + l
        const int j = t & 7;
        const int branch = g >> 2, l = g & 3;
        float rs = 0.0f, is = 0.0f;
        #pragma unroll
        for (int i = j; i < SB; i += 8) {
            rs += reg_sh[(branch * SB + i) * LANES + l];
            is += iou_sh[(branch * SB + i) * LANES + l];
        }
        #pragma unroll
        for (int off = 4; off; off >>= 1) {
            rs += __shfl_down_sync(FULL, rs, off, 8);
            is += __shfl_down_sync(FULL, is, off, 8);
        }
        if (j == 0) {
            float add = rs * (0.5f / 96.0f) + is * (2.0f / 96.0f);
            int r = g_rows[(branch * SB + (SB - 1)) * LANES + l];
            atomicAdd(branch == 0 ? &instA[r] : &instB[r], add);
        }
    }
    __syncthreads();

    // median via dual-rank radix select
    for (int n = tid; n < NPRIOR; n += 1024) {
        float f = instA[n] - instB[n];
        unsigned x = __float_as_uint(f);
        ukey[n] = (x & 0x80000000u) ? ~x : (x | 0x80000000u);
    }
    __syncthreads();

    unsigned prefix[2] = {0u, 0u};
    unsigned mask = 0u;
    int kk[2] = {999, 1000};
    for (int shift = 24; shift >= 0; shift -= 8) {
        if (tid < 512) hist[tid >> 8][tid & 255] = 0;
        __syncthreads();
        for (int n = tid; n < NPRIOR; n += 1024) {
            unsigned u = ukey[n];
            unsigned bin = (u >> shift) & 255u;
            unsigned hi = u & mask;
            if (hi == prefix[0]) atomicAdd(&hist[0][bin], 1);
            if (hi == prefix[1]) atomicAdd(&hist[1][bin], 1);
        }
        __syncthreads();
        if (tid < 64) {
            const int trk = warp;
            int kt = kk[trk];
            int cnt[8]; int local = 0;
            #pragma unroll
            for (int k2 = 0; k2 < 8; k2++) { cnt[k2] = hist[trk][lane * 8 + k2]; local += cnt[k2]; }
            int pre = local;
            #pragma unroll
            for (int off = 1; off < 32; off <<= 1) {
                int t2 = __shfl_up_sync(FULL, pre, off);
                if (lane >= off) pre += t2;
            }
            int run = pre - local;
            int foundk = -1, myrun = 0;
            #pragma unroll
            for (int k2 = 0; k2 < 8; k2++) {
                if (foundk < 0 && kt >= run && kt < run + cnt[k2]) { foundk = k2; myrun = run; }
                run += cnt[k2];
            }
            unsigned bm = __ballot_sync(FULL, foundk >= 0);
            int src = __ffs(bm) - 1;
            if (lane == src) { s_bin[trk] = lane * 8 + foundk; s_k[trk] = kt - myrun; }
        }
        __syncthreads();
        prefix[0] |= ((unsigned)s_bin[0]) << shift;
        prefix[1] |= ((unsigned)s_bin[1]) << shift;
        mask |= 0xFFu << shift;
        kk[0] = s_k[0]; kk[1] = s_k[1];
        __syncthreads();
    }
    float m0 = (prefix[0] & 0x80000000u) ? __uint_as_float(prefix[0] ^ 0x80000000u)
                                         : __uint_as_float(~prefix[0]);
    float m1 = (prefix[1] & 0x80000000u) ? __uint_as_float(prefix[1] ^ 0x80000000u)
                                         : __uint_as_float(~prefix[1]);
    float delta = 0.5f * (m0 + m1);

    // final weighted sum
    float acc = 0.0f;
    for (int n = tid; n < NPRIOR; n += 1024) {
        float dm = (diff[n] + diff[NPRIOR + n] + diff[2 * NPRIOR + n]) * (1.0f / 3.0f);
        acc += (1.0f - dm) * (instA[n] - 0.5f * delta)
             + dm          * (instB[n] + 0.5f * delta);
    }
    red[tid] = acc;
    __syncthreads();
    for (int off = 512; off; off >>= 1) {
        if (tid < off) red[tid] += red[tid + off];
        __syncthreads();
    }
    if (tid == 0) out[0] = red[0];
}

// ---------------------------------------------------------------------------
extern "C" void kernel_launch(void* const* d_in, const int* in_sizes, int n_in,
                              void* d_out, int out_size)
{
    const float* fir  = (const float*)d_in[0];
    const float* sec  = (const float*)d_in[1];
    const float* gt   = (const float*)d_in[2];
    const float* diff = (const float*)d_in[3];
    float* out = (float*)d_out;

    cost_kernel <<<dim3(SB, NTILE, 2), 512>>>(fir, sec, gt);
    match_kernel<<<NTASK, 128>>>(fir, sec, gt);
    final_kernel<<<1, 1024>>>(diff, out);
}